// round 1
// baseline (speedup 1.0000x reference)
#include <cuda_runtime.h>
#include <cstdint>

#define NN 100000
#define EE 1600000

// Scratch (device globals: allocation-free)
__device__ float  g_P[NN * 64];
__device__ float  g_Q[NN * 64];
__device__ float  g_cnt[NN];
__device__ double g_sum[64];
__device__ double g_sq[64];
__device__ float  g_scale[64];
__device__ float  g_shift[64];

// ---------------------------------------------------------------------------
// Kernel 1: P = feat @ (W1-W2)^T, Q = feat @ W2^T   (M=100000, N=128, K=64)
// Block: 256 threads, tile 64 nodes x 128 channels, K fully resident.
// ---------------------------------------------------------------------------
__global__ __launch_bounds__(256) void gemm_pq(const float* __restrict__ feat,
                                               const float* __restrict__ W) {
    __shared__ float Wsh[64][128];  // [k][c']: c'<64 -> W1-W2, c'>=64 -> W2
    __shared__ float Xsh[64][64];   // [node][k]

    for (int i = threadIdx.x; i < 64 * 64; i += 256) {
        int c = i >> 6, k = i & 63;
        float w1 = W[c * 128 + k];
        float w2 = W[c * 128 + 64 + k];
        Wsh[k][c]      = w1 - w2;
        Wsh[k][64 + c] = w2;
    }
    int node0 = blockIdx.x * 64;
    for (int i = threadIdx.x; i < 64 * 16; i += 256) {
        int n = i >> 4, v = i & 15;
        int gn = node0 + n;
        if (gn >= NN) gn = NN - 1;
        float4 x = reinterpret_cast<const float4*>(feat)[gn * 16 + v];
        *reinterpret_cast<float4*>(&Xsh[n][v * 4]) = x;
    }
    __syncthreads();

    const int tx = threadIdx.x & 15;   // channel group: 8 channels
    const int ty = threadIdx.x >> 4;   // node group: 4 nodes
    float acc[4][8];
#pragma unroll
    for (int j = 0; j < 4; j++)
#pragma unroll
        for (int cc = 0; cc < 8; cc++) acc[j][cc] = 0.f;

#pragma unroll 8
    for (int k = 0; k < 64; k++) {
        float4 wa = *reinterpret_cast<const float4*>(&Wsh[k][tx * 8]);
        float4 wb = *reinterpret_cast<const float4*>(&Wsh[k][tx * 8 + 4]);
        float w[8] = {wa.x, wa.y, wa.z, wa.w, wb.x, wb.y, wb.z, wb.w};
#pragma unroll
        for (int j = 0; j < 4; j++) {
            float xv = Xsh[ty * 4 + j][k];
#pragma unroll
            for (int cc = 0; cc < 8; cc++)
                acc[j][cc] = fmaf(xv, w[cc], acc[j][cc]);
        }
    }

    const int cbase = tx * 8;
    float* dstArr = (cbase < 64) ? g_P : g_Q;
    const int coff = cbase & 63;
#pragma unroll
    for (int j = 0; j < 4; j++) {
        int gn = node0 + ty * 4 + j;
        if (gn < NN) {
            float4 o0 = make_float4(acc[j][0], acc[j][1], acc[j][2], acc[j][3]);
            float4 o1 = make_float4(acc[j][4], acc[j][5], acc[j][6], acc[j][7]);
            float4* d = reinterpret_cast<float4*>(&dstArr[gn * 64 + coff]);
            d[0] = o0;
            d[1] = o1;
        }
    }
}

// ---------------------------------------------------------------------------
// Kernel 2: BN statistics over all edges of t = P[dst] + Q[src]  (+ degree cnt)
// Warp handles 2 edges: lanes 0-15 -> edge e, lanes 16-31 -> edge e+1.
// Each 16-lane group loads 64 floats as float4 (lane li owns channels 4li..4li+3).
// ---------------------------------------------------------------------------
__global__ __launch_bounds__(256) void edge_stats(const int* __restrict__ ei) {
    const int lane = threadIdx.x & 31;
    const int li = lane & 15;
    const int sub = lane >> 4;
    const int wg = (blockIdx.x * 256 + threadIdx.x) >> 5;
    const int nw = (gridDim.x * 256) >> 5;
    const float4* P4 = reinterpret_cast<const float4*>(g_P);
    const float4* Q4 = reinterpret_cast<const float4*>(g_Q);

    float4 s  = make_float4(0.f, 0.f, 0.f, 0.f);
    float4 s2 = make_float4(0.f, 0.f, 0.f, 0.f);

    for (int e = wg * 2 + sub; e < EE; e += nw * 2) {
        int src = __ldg(&ei[e]);
        int dst = __ldg(&ei[EE + e]);
        float4 p = P4[dst * 16 + li];
        float4 q = Q4[src * 16 + li];
        float t0 = p.x + q.x, t1 = p.y + q.y, t2 = p.z + q.z, t3 = p.w + q.w;
        s.x += t0; s.y += t1; s.z += t2; s.w += t3;
        s2.x += t0 * t0; s2.y += t1 * t1; s2.z += t2 * t2; s2.w += t3 * t3;
        if (li == 0) atomicAdd(&g_cnt[dst], 1.0f);
    }

    // fold the two 16-lane halves (same channel ownership)
    s.x  += __shfl_down_sync(0xffffffffu, s.x, 16);
    s.y  += __shfl_down_sync(0xffffffffu, s.y, 16);
    s.z  += __shfl_down_sync(0xffffffffu, s.z, 16);
    s.w  += __shfl_down_sync(0xffffffffu, s.w, 16);
    s2.x += __shfl_down_sync(0xffffffffu, s2.x, 16);
    s2.y += __shfl_down_sync(0xffffffffu, s2.y, 16);
    s2.z += __shfl_down_sync(0xffffffffu, s2.z, 16);
    s2.w += __shfl_down_sync(0xffffffffu, s2.w, 16);

    __shared__ float ssum[64], ssq[64];
    if (threadIdx.x < 64) { ssum[threadIdx.x] = 0.f; ssq[threadIdx.x] = 0.f; }
    __syncthreads();
    if (lane < 16) {
        atomicAdd(&ssum[li * 4 + 0], s.x);
        atomicAdd(&ssum[li * 4 + 1], s.y);
        atomicAdd(&ssum[li * 4 + 2], s.z);
        atomicAdd(&ssum[li * 4 + 3], s.w);
        atomicAdd(&ssq[li * 4 + 0], s2.x);
        atomicAdd(&ssq[li * 4 + 1], s2.y);
        atomicAdd(&ssq[li * 4 + 2], s2.z);
        atomicAdd(&ssq[li * 4 + 3], s2.w);
    }
    __syncthreads();
    if (threadIdx.x < 64) {
        atomicAdd(&g_sum[threadIdx.x], (double)ssum[threadIdx.x]);
        atomicAdd(&g_sq[threadIdx.x], (double)ssq[threadIdx.x]);
    }
}

// ---------------------------------------------------------------------------
// Kernel 3: fold BN into per-channel scale/shift.
// m = t + b; mu = mean(t) + b  =>  m - mu = t - mean(t); var(m) = var(t).
// y = t*scale + shift with scale = gamma*rsqrt(var+eps), shift = beta - mean*scale.
// ---------------------------------------------------------------------------
__global__ void bn_finalize(const float* __restrict__ gamma,
                            const float* __restrict__ beta) {
    int c = threadIdx.x;
    double inv_e = 1.0 / (double)EE;
    double mean = g_sum[c] * inv_e;
    double var = g_sq[c] * inv_e - mean * mean;
    float scale = gamma[c] * rsqrtf((float)var + 1e-5f);
    g_scale[c] = scale;
    g_shift[c] = fmaf(-(float)mean, scale, beta[c]);
}

// ---------------------------------------------------------------------------
// Kernel 4: per-edge normalize + LeakyReLU + scatter-add via red.global.v4.f32
// ---------------------------------------------------------------------------
__global__ __launch_bounds__(256) void edge_scatter(const int* __restrict__ ei,
                                                    float* __restrict__ out) {
    const int lane = threadIdx.x & 31;
    const int li = lane & 15;
    const int sub = lane >> 4;
    const int wg = (blockIdx.x * 256 + threadIdx.x) >> 5;
    const int nw = (gridDim.x * 256) >> 5;
    const float4* P4 = reinterpret_cast<const float4*>(g_P);
    const float4* Q4 = reinterpret_cast<const float4*>(g_Q);
    const float4 sc = reinterpret_cast<const float4*>(g_scale)[li];
    const float4 sh = reinterpret_cast<const float4*>(g_shift)[li];

    for (int e = wg * 2 + sub; e < EE; e += nw * 2) {
        int src = __ldg(&ei[e]);
        int dst = __ldg(&ei[EE + e]);
        float4 p = P4[dst * 16 + li];
        float4 q = Q4[src * 16 + li];
        float y0 = fmaf(p.x + q.x, sc.x, sh.x);
        float y1 = fmaf(p.y + q.y, sc.y, sh.y);
        float y2 = fmaf(p.z + q.z, sc.z, sh.z);
        float y3 = fmaf(p.w + q.w, sc.w, sh.w);
        y0 = y0 >= 0.f ? y0 : 0.3f * y0;
        y1 = y1 >= 0.f ? y1 : 0.3f * y1;
        y2 = y2 >= 0.f ? y2 : 0.3f * y2;
        y3 = y3 >= 0.f ? y3 : 0.3f * y3;
        float* ptr = out + (size_t)dst * 64 + li * 4;
        asm volatile("red.global.add.v4.f32 [%0], {%1, %2, %3, %4};"
                     :: "l"(ptr), "f"(y0), "f"(y1), "f"(y2), "f"(y3)
                     : "memory");
    }
}

// ---------------------------------------------------------------------------
// Kernel 5: divide by clamped degree (mean aggregation)
// ---------------------------------------------------------------------------
__global__ __launch_bounds__(256) void div_by_cnt(float* __restrict__ out) {
    int i = blockIdx.x * 256 + threadIdx.x;
    if (i >= NN * 16) return;
    int n = i >> 4;
    float inv = 1.0f / fmaxf(g_cnt[n], 1.0f);
    float4* o = reinterpret_cast<float4*>(out);
    float4 v = o[i];
    v.x *= inv; v.y *= inv; v.z *= inv; v.w *= inv;
    o[i] = v;
}

// ---------------------------------------------------------------------------
extern "C" void kernel_launch(void* const* d_in, const int* in_sizes, int n_in,
                              void* d_out, int out_size) {
    const float* feat  = (const float*)d_in[0];
    const int*   ei    = (const int*)d_in[1];
    const float* W     = (const float*)d_in[2];
    // d_in[3] = b: cancels out of BN, unused
    const float* gamma = (const float*)d_in[4];
    const float* beta  = (const float*)d_in[5];
    float* out = (float*)d_out;

    void *p_cnt, *p_sum, *p_sq;
    cudaGetSymbolAddress(&p_cnt, g_cnt);
    cudaGetSymbolAddress(&p_sum, g_sum);
    cudaGetSymbolAddress(&p_sq,  g_sq);

    cudaMemsetAsync(out, 0, (size_t)NN * 64 * sizeof(float));
    cudaMemsetAsync(p_cnt, 0, (size_t)NN * sizeof(float));
    cudaMemsetAsync(p_sum, 0, 64 * sizeof(double));
    cudaMemsetAsync(p_sq,  0, 64 * sizeof(double));

    gemm_pq<<<(NN + 63) / 64, 256>>>(feat, W);
    edge_stats<<<592, 256>>>(ei);
    bn_finalize<<<1, 64>>>(gamma, beta);
    edge_scatter<<<1480, 256>>>(ei, out);
    div_by_cnt<<<(NN * 16 + 255) / 256, 256>>>(out);
}

// round 2
// speedup vs baseline: 1.2210x; 1.2210x over previous
#include <cuda_runtime.h>
#include <cuda_fp16.h>
#include <cstdint>

#define NN 100000
#define EE 1600000

// Scratch (device globals: allocation-free)
__device__ float  g_P[NN * 64];    // fp32 P (for scatter accuracy)
__device__ __half g_Ph[NN * 64];   // fp16 P (stats pass)
__device__ __half g_Qh[NN * 64];   // fp16 Q (both passes)
__device__ float  g_cnt[NN];
__device__ float  g_inv[NN];
__device__ double g_sum[64];
__device__ double g_sq[64];
__device__ float  g_scale[64];
__device__ float  g_shift[64];

// ---------------------------------------------------------------------------
// Kernel 1: P = feat @ (W1-W2)^T (fp32+fp16), Q = feat @ W2^T (fp16)
// ---------------------------------------------------------------------------
__global__ __launch_bounds__(256) void gemm_pq(const float* __restrict__ feat,
                                               const float* __restrict__ W) {
    __shared__ float Wsh[64][128];  // [k][c']: c'<64 -> W1-W2, c'>=64 -> W2
    __shared__ float Xsh[64][64];   // [node][k]

    for (int i = threadIdx.x; i < 64 * 64; i += 256) {
        int c = i >> 6, k = i & 63;
        float w1 = W[c * 128 + k];
        float w2 = W[c * 128 + 64 + k];
        Wsh[k][c]      = w1 - w2;
        Wsh[k][64 + c] = w2;
    }
    int node0 = blockIdx.x * 64;
    for (int i = threadIdx.x; i < 64 * 16; i += 256) {
        int n = i >> 4, v = i & 15;
        int gn = node0 + n;
        if (gn >= NN) gn = NN - 1;
        float4 x = reinterpret_cast<const float4*>(feat)[gn * 16 + v];
        *reinterpret_cast<float4*>(&Xsh[n][v * 4]) = x;
    }
    __syncthreads();

    const int tx = threadIdx.x & 15;   // channel group: 8 channels
    const int ty = threadIdx.x >> 4;   // node group: 4 nodes
    float acc[4][8];
#pragma unroll
    for (int j = 0; j < 4; j++)
#pragma unroll
        for (int cc = 0; cc < 8; cc++) acc[j][cc] = 0.f;

#pragma unroll 8
    for (int k = 0; k < 64; k++) {
        float4 wa = *reinterpret_cast<const float4*>(&Wsh[k][tx * 8]);
        float4 wb = *reinterpret_cast<const float4*>(&Wsh[k][tx * 8 + 4]);
        float w[8] = {wa.x, wa.y, wa.z, wa.w, wb.x, wb.y, wb.z, wb.w};
#pragma unroll
        for (int j = 0; j < 4; j++) {
            float xv = Xsh[ty * 4 + j][k];
#pragma unroll
            for (int cc = 0; cc < 8; cc++)
                acc[j][cc] = fmaf(xv, w[cc], acc[j][cc]);
        }
    }

    const int cbase = tx * 8;
#pragma unroll
    for (int j = 0; j < 4; j++) {
        int gn = node0 + ty * 4 + j;
        if (gn >= NN) continue;
        // pack fp16
        uint4 hv;
        *reinterpret_cast<__half2*>(&hv.x) = __floats2half2_rn(acc[j][0], acc[j][1]);
        *reinterpret_cast<__half2*>(&hv.y) = __floats2half2_rn(acc[j][2], acc[j][3]);
        *reinterpret_cast<__half2*>(&hv.z) = __floats2half2_rn(acc[j][4], acc[j][5]);
        *reinterpret_cast<__half2*>(&hv.w) = __floats2half2_rn(acc[j][6], acc[j][7]);
        if (cbase < 64) {
            float4* d = reinterpret_cast<float4*>(&g_P[gn * 64 + cbase]);
            d[0] = make_float4(acc[j][0], acc[j][1], acc[j][2], acc[j][3]);
            d[1] = make_float4(acc[j][4], acc[j][5], acc[j][6], acc[j][7]);
            *reinterpret_cast<uint4*>(&g_Ph[gn * 64 + cbase]) = hv;
        } else {
            *reinterpret_cast<uint4*>(&g_Qh[gn * 64 + (cbase - 64)]) = hv;
        }
    }
}

// ---------------------------------------------------------------------------
// Kernel 2: BN statistics over t = Ph[dst] + Qh[src] (fp16 gathers, fp32 accum)
// 8 lanes per edge (128B row = 8 x uint4), warp = 4 edges.
// ---------------------------------------------------------------------------
__global__ __launch_bounds__(256) void edge_stats(const int* __restrict__ ei) {
    const int lane = threadIdx.x & 31;
    const int li = lane & 7;
    const int sub = lane >> 3;
    const int wg = (blockIdx.x * 256 + threadIdx.x) >> 5;
    const int nw = (gridDim.x * 256) >> 5;
    const uint4* P8 = reinterpret_cast<const uint4*>(g_Ph);
    const uint4* Q8 = reinterpret_cast<const uint4*>(g_Qh);

    float s[8], s2[8];
#pragma unroll
    for (int j = 0; j < 8; j++) { s[j] = 0.f; s2[j] = 0.f; }

    for (int e = wg * 4 + sub; e < EE; e += nw * 4) {
        int src = __ldg(&ei[e]);
        int dst = __ldg(&ei[EE + e]);
        uint4 ph = P8[dst * 8 + li];
        uint4 qh = Q8[src * 8 + li];
        const unsigned pw[4] = {ph.x, ph.y, ph.z, ph.w};
        const unsigned qw[4] = {qh.x, qh.y, qh.z, qh.w};
#pragma unroll
        for (int w = 0; w < 4; w++) {
            float2 pf = __half22float2(*reinterpret_cast<const __half2*>(&pw[w]));
            float2 qf = __half22float2(*reinterpret_cast<const __half2*>(&qw[w]));
            float t0 = pf.x + qf.x, t1 = pf.y + qf.y;
            s[w * 2]      += t0;      s[w * 2 + 1]  += t1;
            s2[w * 2]     += t0 * t0; s2[w * 2 + 1] += t1 * t1;
        }
        if (li == 0) atomicAdd(&g_cnt[dst], 1.0f);
    }

#pragma unroll
    for (int j = 0; j < 8; j++) {
        s[j]  += __shfl_down_sync(0xffffffffu, s[j], 16);
        s[j]  += __shfl_down_sync(0xffffffffu, s[j], 8);
        s2[j] += __shfl_down_sync(0xffffffffu, s2[j], 16);
        s2[j] += __shfl_down_sync(0xffffffffu, s2[j], 8);
    }

    __shared__ float ssum[64], ssq[64];
    if (threadIdx.x < 64) { ssum[threadIdx.x] = 0.f; ssq[threadIdx.x] = 0.f; }
    __syncthreads();
    if (lane < 8) {
#pragma unroll
        for (int j = 0; j < 8; j++) {
            atomicAdd(&ssum[li * 8 + j], s[j]);
            atomicAdd(&ssq[li * 8 + j], s2[j]);
        }
    }
    __syncthreads();
    if (threadIdx.x < 64) {
        atomicAdd(&g_sum[threadIdx.x], (double)ssum[threadIdx.x]);
        atomicAdd(&g_sq[threadIdx.x], (double)ssq[threadIdx.x]);
    }
}

// ---------------------------------------------------------------------------
// Kernel 3: fold BN into per-channel scale/shift (b cancels out of BN).
// ---------------------------------------------------------------------------
__global__ void bn_finalize(const float* __restrict__ gamma,
                            const float* __restrict__ beta) {
    int c = threadIdx.x;
    double inv_e = 1.0 / (double)EE;
    double mean = g_sum[c] * inv_e;
    double var = g_sq[c] * inv_e - mean * mean;
    float scale = gamma[c] * rsqrtf((float)var + 1e-5f);
    g_scale[c] = scale;
    g_shift[c] = fmaf(-(float)mean, scale, beta[c]);
}

// ---------------------------------------------------------------------------
// Kernel 3b: reciprocal degree
// ---------------------------------------------------------------------------
__global__ __launch_bounds__(256) void inv_cnt() {
    int i = blockIdx.x * 256 + threadIdx.x;
    if (i < NN) g_inv[i] = 1.0f / fmaxf(g_cnt[i], 1.0f);
}

// ---------------------------------------------------------------------------
// Kernel 4: normalize + LeakyReLU + mean-weight + scatter (red.global.v4.f32)
// P fp32 (accuracy-critical, dst-correlated), Q fp16 (error averages out).
// 16 lanes per edge, warp = 2 edges.
// ---------------------------------------------------------------------------
__global__ __launch_bounds__(256) void edge_scatter(const int* __restrict__ ei,
                                                    float* __restrict__ out) {
    const int lane = threadIdx.x & 31;
    const int li = lane & 15;
    const int sub = lane >> 4;
    const int wg = (blockIdx.x * 256 + threadIdx.x) >> 5;
    const int nw = (gridDim.x * 256) >> 5;
    const float4* P4 = reinterpret_cast<const float4*>(g_P);
    const uint2* Q2 = reinterpret_cast<const uint2*>(g_Qh);  // 4 halves each
    const float4 sc = reinterpret_cast<const float4*>(g_scale)[li];
    const float4 sh = reinterpret_cast<const float4*>(g_shift)[li];

    for (int e = wg * 2 + sub; e < EE; e += nw * 2) {
        int src = __ldg(&ei[e]);
        int dst = __ldg(&ei[EE + e]);
        float4 p = P4[dst * 16 + li];
        uint2 qw = Q2[src * 16 + li];
        float inv = __ldg(&g_inv[dst]);
        float2 q01 = __half22float2(*reinterpret_cast<const __half2*>(&qw.x));
        float2 q23 = __half22float2(*reinterpret_cast<const __half2*>(&qw.y));
        float y0 = fmaf(p.x + q01.x, sc.x, sh.x);
        float y1 = fmaf(p.y + q01.y, sc.y, sh.y);
        float y2 = fmaf(p.z + q23.x, sc.z, sh.z);
        float y3 = fmaf(p.w + q23.y, sc.w, sh.w);
        y0 = (y0 >= 0.f ? y0 : 0.3f * y0) * inv;
        y1 = (y1 >= 0.f ? y1 : 0.3f * y1) * inv;
        y2 = (y2 >= 0.f ? y2 : 0.3f * y2) * inv;
        y3 = (y3 >= 0.f ? y3 : 0.3f * y3) * inv;
        float* ptr = out + (size_t)dst * 64 + li * 4;
        asm volatile("red.global.add.v4.f32 [%0], {%1, %2, %3, %4};"
                     :: "l"(ptr), "f"(y0), "f"(y1), "f"(y2), "f"(y3)
                     : "memory");
    }
}

// ---------------------------------------------------------------------------
extern "C" void kernel_launch(void* const* d_in, const int* in_sizes, int n_in,
                              void* d_out, int out_size) {
    const float* feat  = (const float*)d_in[0];
    const int*   ei    = (const int*)d_in[1];
    const float* W     = (const float*)d_in[2];
    // d_in[3] = b: cancels out of BN, unused
    const float* gamma = (const float*)d_in[4];
    const float* beta  = (const float*)d_in[5];
    float* out = (float*)d_out;

    void *p_cnt, *p_sum, *p_sq;
    cudaGetSymbolAddress(&p_cnt, g_cnt);
    cudaGetSymbolAddress(&p_sum, g_sum);
    cudaGetSymbolAddress(&p_sq,  g_sq);

    cudaMemsetAsync(out, 0, (size_t)NN * 64 * sizeof(float));
    cudaMemsetAsync(p_cnt, 0, (size_t)NN * sizeof(float));
    cudaMemsetAsync(p_sum, 0, 64 * sizeof(double));
    cudaMemsetAsync(p_sq,  0, 64 * sizeof(double));

    gemm_pq<<<(NN + 63) / 64, 256>>>(feat, W);
    edge_stats<<<592, 256>>>(ei);
    bn_finalize<<<1, 64>>>(gamma, beta);
    inv_cnt<<<(NN + 255) / 256, 256>>>();
    edge_scatter<<<1480, 256>>>(ei, out);
}

// round 3
// speedup vs baseline: 1.2224x; 1.0012x over previous
#include <cuda_runtime.h>
#include <cuda_fp16.h>
#include <cstdint>

#define NN 100000
#define EE 1600000
#define GEMM_BLOCKS ((NN + 63) / 64)
#define CNT_BLOCKS 160

// Scratch (device globals: allocation-free)
__device__ __half g_Ph[NN * 64];   // fp16 P = feat @ (W1-W2)^T
__device__ __half g_Qh[NN * 64];   // fp16 Q = feat @ W2^T
__device__ float  g_cnt[NN];
__device__ float  g_inv[NN];
__device__ double g_stats[128];    // [0:64) sum, [64:128) sumsq
__device__ float  g_scale[64];
__device__ float  g_shift[64];

// ---------------------------------------------------------------------------
// Kernel 1: heterogeneous launch.
//   blocks [0, GEMM_BLOCKS): P/Q projection GEMM (fp16 outputs)
//   blocks [GEMM_BLOCKS, +CNT_BLOCKS): degree count atomics (overlaps GEMM)
// ---------------------------------------------------------------------------
__global__ __launch_bounds__(256) void gemm_pq_cnt(const float* __restrict__ feat,
                                                   const float* __restrict__ W,
                                                   const int* __restrict__ ei) {
    if (blockIdx.x >= GEMM_BLOCKS) {
        // degree-count blocks
        int t0 = (blockIdx.x - GEMM_BLOCKS) * 256 + threadIdx.x;
        int stride = CNT_BLOCKS * 256;
        for (int e = t0; e < EE; e += stride) {
            int dst = __ldg(&ei[EE + e]);
            atomicAdd(&g_cnt[dst], 1.0f);
        }
        return;
    }

    __shared__ float Wsh[64][128];  // [k][c']: c'<64 -> W1-W2, c'>=64 -> W2
    __shared__ float Xsh[64][64];   // [node][k]

    for (int i = threadIdx.x; i < 64 * 64; i += 256) {
        int c = i >> 6, k = i & 63;
        float w1 = W[c * 128 + k];
        float w2 = W[c * 128 + 64 + k];
        Wsh[k][c]      = w1 - w2;
        Wsh[k][64 + c] = w2;
    }
    int node0 = blockIdx.x * 64;
    for (int i = threadIdx.x; i < 64 * 16; i += 256) {
        int n = i >> 4, v = i & 15;
        int gn = node0 + n;
        if (gn >= NN) gn = NN - 1;
        float4 x = reinterpret_cast<const float4*>(feat)[gn * 16 + v];
        *reinterpret_cast<float4*>(&Xsh[n][v * 4]) = x;
    }
    __syncthreads();

    const int tx = threadIdx.x & 15;   // channel group: 8 channels
    const int ty = threadIdx.x >> 4;   // node group: 4 nodes
    float acc[4][8];
#pragma unroll
    for (int j = 0; j < 4; j++)
#pragma unroll
        for (int cc = 0; cc < 8; cc++) acc[j][cc] = 0.f;

#pragma unroll 8
    for (int k = 0; k < 64; k++) {
        float4 wa = *reinterpret_cast<const float4*>(&Wsh[k][tx * 8]);
        float4 wb = *reinterpret_cast<const float4*>(&Wsh[k][tx * 8 + 4]);
        float w[8] = {wa.x, wa.y, wa.z, wa.w, wb.x, wb.y, wb.z, wb.w};
#pragma unroll
        for (int j = 0; j < 4; j++) {
            float xv = Xsh[ty * 4 + j][k];
#pragma unroll
            for (int cc = 0; cc < 8; cc++)
                acc[j][cc] = fmaf(xv, w[cc], acc[j][cc]);
        }
    }

    const int cbase = tx * 8;
#pragma unroll
    for (int j = 0; j < 4; j++) {
        int gn = node0 + ty * 4 + j;
        if (gn >= NN) continue;
        uint4 hv;
        *reinterpret_cast<__half2*>(&hv.x) = __floats2half2_rn(acc[j][0], acc[j][1]);
        *reinterpret_cast<__half2*>(&hv.y) = __floats2half2_rn(acc[j][2], acc[j][3]);
        *reinterpret_cast<__half2*>(&hv.z) = __floats2half2_rn(acc[j][4], acc[j][5]);
        *reinterpret_cast<__half2*>(&hv.w) = __floats2half2_rn(acc[j][6], acc[j][7]);
        __half* base = (cbase < 64) ? &g_Ph[gn * 64 + cbase]
                                    : &g_Qh[gn * 64 + (cbase - 64)];
        *reinterpret_cast<uint4*>(base) = hv;
    }
}

// ---------------------------------------------------------------------------
// Kernel 2: BN statistics over t = Ph[dst] + Qh[src] (fp16 gathers, fp32 accum)
// Head: also fills g_inv (g_cnt is final after kernel 1).
// 8 lanes per edge (128B row = 8 x uint4), warp = 4 edges.
// ---------------------------------------------------------------------------
__global__ __launch_bounds__(256) void edge_stats(const int* __restrict__ ei) {
    // fused reciprocal-degree (cheap, overlaps with first gathers elsewhere)
    {
        int gid = blockIdx.x * 256 + threadIdx.x;
        int tot = gridDim.x * 256;
        for (int i = gid; i < NN; i += tot)
            g_inv[i] = 1.0f / fmaxf(g_cnt[i], 1.0f);
    }

    const int lane = threadIdx.x & 31;
    const int li = lane & 7;
    const int sub = lane >> 3;
    const int wg = (blockIdx.x * 256 + threadIdx.x) >> 5;
    const int nw = (gridDim.x * 256) >> 5;
    const uint4* P8 = reinterpret_cast<const uint4*>(g_Ph);
    const uint4* Q8 = reinterpret_cast<const uint4*>(g_Qh);

    float s[8], s2[8];
#pragma unroll
    for (int j = 0; j < 8; j++) { s[j] = 0.f; s2[j] = 0.f; }

    for (int e = wg * 4 + sub; e < EE; e += nw * 4) {
        int src = __ldg(&ei[e]);
        int dst = __ldg(&ei[EE + e]);
        uint4 ph = P8[dst * 8 + li];
        uint4 qh = Q8[src * 8 + li];
        const unsigned pw[4] = {ph.x, ph.y, ph.z, ph.w};
        const unsigned qw[4] = {qh.x, qh.y, qh.z, qh.w};
#pragma unroll
        for (int w = 0; w < 4; w++) {
            float2 pf = __half22float2(*reinterpret_cast<const __half2*>(&pw[w]));
            float2 qf = __half22float2(*reinterpret_cast<const __half2*>(&qw[w]));
            float t0 = pf.x + qf.x, t1 = pf.y + qf.y;
            s[w * 2]      += t0;      s[w * 2 + 1]  += t1;
            s2[w * 2]     += t0 * t0; s2[w * 2 + 1] += t1 * t1;
        }
    }

#pragma unroll
    for (int j = 0; j < 8; j++) {
        s[j]  += __shfl_down_sync(0xffffffffu, s[j], 16);
        s[j]  += __shfl_down_sync(0xffffffffu, s[j], 8);
        s2[j] += __shfl_down_sync(0xffffffffu, s2[j], 16);
        s2[j] += __shfl_down_sync(0xffffffffu, s2[j], 8);
    }

    __shared__ float ssum[64], ssq[64];
    if (threadIdx.x < 64) { ssum[threadIdx.x] = 0.f; ssq[threadIdx.x] = 0.f; }
    __syncthreads();
    if (lane < 8) {
#pragma unroll
        for (int j = 0; j < 8; j++) {
            atomicAdd(&ssum[li * 8 + j], s[j]);
            atomicAdd(&ssq[li * 8 + j], s2[j]);
        }
    }
    __syncthreads();
    if (threadIdx.x < 64) {
        atomicAdd(&g_stats[threadIdx.x], (double)ssum[threadIdx.x]);
        atomicAdd(&g_stats[64 + threadIdx.x], (double)ssq[threadIdx.x]);
    }
}

// ---------------------------------------------------------------------------
// Kernel 3: fold BN into per-channel scale/shift (b cancels out of BN).
// ---------------------------------------------------------------------------
__global__ void bn_finalize(const float* __restrict__ gamma,
                            const float* __restrict__ beta) {
    int c = threadIdx.x;
    double inv_e = 1.0 / (double)EE;
    double mean = g_stats[c] * inv_e;
    double var = g_stats[64 + c] * inv_e - mean * mean;
    float scale = gamma[c] * rsqrtf((float)var + 1e-5f);
    g_scale[c] = scale;
    g_shift[c] = fmaf(-(float)mean, scale, beta[c]);
}

// ---------------------------------------------------------------------------
// Kernel 4: normalize + LeakyReLU + mean-weight + scatter (red.global.v4.f32)
// All-fp16 gathers (256 B/edge). 8 lanes per edge, warp = 4 edges.
// ---------------------------------------------------------------------------
__global__ __launch_bounds__(256) void edge_scatter(const int* __restrict__ ei,
                                                    float* __restrict__ out) {
    const int lane = threadIdx.x & 31;
    const int li = lane & 7;
    const int sub = lane >> 3;
    const int wg = (blockIdx.x * 256 + threadIdx.x) >> 5;
    const int nw = (gridDim.x * 256) >> 5;
    const uint4* P8 = reinterpret_cast<const uint4*>(g_Ph);
    const uint4* Q8 = reinterpret_cast<const uint4*>(g_Qh);
    const float4 sc0 = reinterpret_cast<const float4*>(g_scale)[li * 2];
    const float4 sc1 = reinterpret_cast<const float4*>(g_scale)[li * 2 + 1];
    const float4 sh0 = reinterpret_cast<const float4*>(g_shift)[li * 2];
    const float4 sh1 = reinterpret_cast<const float4*>(g_shift)[li * 2 + 1];

    for (int e = wg * 4 + sub; e < EE; e += nw * 4) {
        int src = __ldg(&ei[e]);
        int dst = __ldg(&ei[EE + e]);
        uint4 ph = P8[dst * 8 + li];
        uint4 qh = Q8[src * 8 + li];
        float inv = __ldg(&g_inv[dst]);
        const unsigned pw[4] = {ph.x, ph.y, ph.z, ph.w};
        const unsigned qw[4] = {qh.x, qh.y, qh.z, qh.w};
        float y[8];
        const float scv[8] = {sc0.x, sc0.y, sc0.z, sc0.w, sc1.x, sc1.y, sc1.z, sc1.w};
        const float shv[8] = {sh0.x, sh0.y, sh0.z, sh0.w, sh1.x, sh1.y, sh1.z, sh1.w};
#pragma unroll
        for (int w = 0; w < 4; w++) {
            float2 pf = __half22float2(*reinterpret_cast<const __half2*>(&pw[w]));
            float2 qf = __half22float2(*reinterpret_cast<const __half2*>(&qw[w]));
            float t0 = pf.x + qf.x, t1 = pf.y + qf.y;
            float v0 = fmaf(t0, scv[w * 2], shv[w * 2]);
            float v1 = fmaf(t1, scv[w * 2 + 1], shv[w * 2 + 1]);
            y[w * 2]     = (v0 >= 0.f ? v0 : 0.3f * v0) * inv;
            y[w * 2 + 1] = (v1 >= 0.f ? v1 : 0.3f * v1) * inv;
        }
        float* ptr = out + (size_t)dst * 64 + li * 8;
        asm volatile("red.global.add.v4.f32 [%0], {%1, %2, %3, %4};"
                     :: "l"(ptr), "f"(y[0]), "f"(y[1]), "f"(y[2]), "f"(y[3])
                     : "memory");
        asm volatile("red.global.add.v4.f32 [%0], {%1, %2, %3, %4};"
                     :: "l"(ptr + 4), "f"(y[4]), "f"(y[5]), "f"(y[6]), "f"(y[7])
                     : "memory");
    }
}

// ---------------------------------------------------------------------------
extern "C" void kernel_launch(void* const* d_in, const int* in_sizes, int n_in,
                              void* d_out, int out_size) {
    const float* feat  = (const float*)d_in[0];
    const int*   ei    = (const int*)d_in[1];
    const float* W     = (const float*)d_in[2];
    // d_in[3] = b: cancels out of BN, unused
    const float* gamma = (const float*)d_in[4];
    const float* beta  = (const float*)d_in[5];
    float* out = (float*)d_out;

    void *p_cnt, *p_stats;
    cudaGetSymbolAddress(&p_cnt, g_cnt);
    cudaGetSymbolAddress(&p_stats, g_stats);

    cudaMemsetAsync(out, 0, (size_t)NN * 64 * sizeof(float));
    cudaMemsetAsync(p_cnt, 0, (size_t)NN * sizeof(float));
    cudaMemsetAsync(p_stats, 0, 128 * sizeof(double));

    gemm_pq_cnt<<<GEMM_BLOCKS + CNT_BLOCKS, 256>>>(feat, W, ei);
    edge_stats<<<1184, 256>>>(ei);
    bn_finalize<<<1, 64>>>(gamma, beta);
    edge_scatter<<<1480, 256>>>(ei, out);
}

// round 4
// speedup vs baseline: 1.5009x; 1.2278x over previous
#include <cuda_runtime.h>
#include <cuda_fp16.h>
#include <cstdint>

#define NN 100000
#define EE 1600000
#define GEMM_BLOCKS ((NN + 63) / 64)
#define CNT_BLOCKS 160
#define SCAN_BLOCKS ((NN + 1023) / 1024)   // 98

// Scratch (device globals: allocation-free)
__device__ __half g_Ph[NN * 64];   // fp16 P = feat @ (W1-W2)^T
__device__ __half g_Qh[NN * 64];   // fp16 Q = feat @ W2^T
__device__ int    g_cnt[NN];       // in-degree
__device__ int    g_off[NN];       // CSR row offsets
__device__ int    g_cursor[NN];    // fill cursors
__device__ int    g_bsum[SCAN_BLOCKS];
__device__ int    g_boff[SCAN_BLOCKS];
__device__ int    g_csr[EE];       // src indices sorted by dst
__device__ double g_stats[128];    // [0:64) sum, [64:128) sumsq
__device__ float  g_scale[64];
__device__ float  g_shift[64];

// ---------------------------------------------------------------------------
// Kernel 1: heterogeneous launch: GEMM blocks + degree-count blocks.
// ---------------------------------------------------------------------------
__global__ __launch_bounds__(256) void gemm_pq_cnt(const float* __restrict__ feat,
                                                   const float* __restrict__ W,
                                                   const int* __restrict__ ei) {
    if (blockIdx.x >= GEMM_BLOCKS) {
        int t0 = (blockIdx.x - GEMM_BLOCKS) * 256 + threadIdx.x;
        int stride = CNT_BLOCKS * 256;
        for (int e = t0; e < EE; e += stride) {
            int dst = __ldg(&ei[EE + e]);
            atomicAdd(&g_cnt[dst], 1);
        }
        return;
    }

    __shared__ float Wsh[64][128];  // [k][c']: c'<64 -> W1-W2, c'>=64 -> W2
    __shared__ float Xsh[64][64];   // [node][k]

    for (int i = threadIdx.x; i < 64 * 64; i += 256) {
        int c = i >> 6, k = i & 63;
        float w1 = W[c * 128 + k];
        float w2 = W[c * 128 + 64 + k];
        Wsh[k][c]      = w1 - w2;
        Wsh[k][64 + c] = w2;
    }
    int node0 = blockIdx.x * 64;
    for (int i = threadIdx.x; i < 64 * 16; i += 256) {
        int n = i >> 4, v = i & 15;
        int gn = node0 + n;
        if (gn >= NN) gn = NN - 1;
        float4 x = reinterpret_cast<const float4*>(feat)[gn * 16 + v];
        *reinterpret_cast<float4*>(&Xsh[n][v * 4]) = x;
    }
    __syncthreads();

    const int tx = threadIdx.x & 15;   // channel group: 8 channels
    const int ty = threadIdx.x >> 4;   // node group: 4 nodes
    float acc[4][8];
#pragma unroll
    for (int j = 0; j < 4; j++)
#pragma unroll
        for (int cc = 0; cc < 8; cc++) acc[j][cc] = 0.f;

#pragma unroll
    for (int k0 = 0; k0 < 64; k0 += 4) {
        float4 xr[4];
#pragma unroll
        for (int j = 0; j < 4; j++)
            xr[j] = *reinterpret_cast<const float4*>(&Xsh[ty * 4 + j][k0]);
#pragma unroll
        for (int kk = 0; kk < 4; kk++) {
            float4 wa = *reinterpret_cast<const float4*>(&Wsh[k0 + kk][tx * 8]);
            float4 wb = *reinterpret_cast<const float4*>(&Wsh[k0 + kk][tx * 8 + 4]);
            float w[8] = {wa.x, wa.y, wa.z, wa.w, wb.x, wb.y, wb.z, wb.w};
#pragma unroll
            for (int j = 0; j < 4; j++) {
                float xv = reinterpret_cast<const float*>(&xr[j])[kk];
#pragma unroll
                for (int cc = 0; cc < 8; cc++)
                    acc[j][cc] = fmaf(xv, w[cc], acc[j][cc]);
            }
        }
    }

    const int cbase = tx * 8;
#pragma unroll
    for (int j = 0; j < 4; j++) {
        int gn = node0 + ty * 4 + j;
        if (gn >= NN) continue;
        uint4 hv;
        *reinterpret_cast<__half2*>(&hv.x) = __floats2half2_rn(acc[j][0], acc[j][1]);
        *reinterpret_cast<__half2*>(&hv.y) = __floats2half2_rn(acc[j][2], acc[j][3]);
        *reinterpret_cast<__half2*>(&hv.z) = __floats2half2_rn(acc[j][4], acc[j][5]);
        *reinterpret_cast<__half2*>(&hv.w) = __floats2half2_rn(acc[j][6], acc[j][7]);
        __half* base = (cbase < 64) ? &g_Ph[gn * 64 + cbase]
                                    : &g_Qh[gn * 64 + (cbase - 64)];
        *reinterpret_cast<uint4*>(base) = hv;
    }
}

// ---------------------------------------------------------------------------
// Kernel 2a: per-1024-chunk exclusive scan of g_cnt -> g_off; chunk totals.
// ---------------------------------------------------------------------------
__global__ __launch_bounds__(1024) void scan_local() {
    __shared__ int wsum[32];
    int i = blockIdx.x * 1024 + threadIdx.x;
    int v = (i < NN) ? g_cnt[i] : 0;
    int lane = threadIdx.x & 31, wid = threadIdx.x >> 5;
    int x = v;
#pragma unroll
    for (int d = 1; d < 32; d <<= 1) {
        int y = __shfl_up_sync(0xffffffffu, x, d);
        if (lane >= d) x += y;
    }
    if (lane == 31) wsum[wid] = x;
    __syncthreads();
    if (wid == 0) {
        int w = wsum[lane];
#pragma unroll
        for (int d = 1; d < 32; d <<= 1) {
            int y = __shfl_up_sync(0xffffffffu, w, d);
            if (lane >= d) w += y;
        }
        wsum[lane] = w;
    }
    __syncthreads();
    int base = (wid > 0) ? wsum[wid - 1] : 0;
    if (i < NN) g_off[i] = base + x - v;
    if (threadIdx.x == 1023) g_bsum[blockIdx.x] = base + x;
}

// ---------------------------------------------------------------------------
// Kernel 2b: exclusive scan of the chunk totals (SCAN_BLOCKS <= 128 values).
// ---------------------------------------------------------------------------
__global__ __launch_bounds__(128) void scan_bsum() {
    __shared__ int ws[4];
    int t = threadIdx.x;
    int v = (t < SCAN_BLOCKS) ? g_bsum[t] : 0;
    int lane = t & 31, wid = t >> 5;
    int x = v;
#pragma unroll
    for (int d = 1; d < 32; d <<= 1) {
        int y = __shfl_up_sync(0xffffffffu, x, d);
        if (lane >= d) x += y;
    }
    if (lane == 31) ws[wid] = x;
    __syncthreads();
    if (t == 0) {
        int r = 0;
#pragma unroll
        for (int k = 0; k < 4; k++) { int tmp = ws[k]; ws[k] = r; r += tmp; }
    }
    __syncthreads();
    if (t < SCAN_BLOCKS) g_boff[t] = ws[wid] + x - v;
}

// ---------------------------------------------------------------------------
// Kernel 2c: finalize offsets, init cursors.
// ---------------------------------------------------------------------------
__global__ __launch_bounds__(256) void off_cursor() {
    int i = blockIdx.x * 256 + threadIdx.x;
    if (i < NN) {
        int o = g_off[i] + g_boff[i >> 10];
        g_off[i] = o;
        g_cursor[i] = o;
    }
}

// ---------------------------------------------------------------------------
// Kernel 3: CSR fill (counting-sort edges by dst).
// ---------------------------------------------------------------------------
__global__ __launch_bounds__(256) void csr_fill(const int* __restrict__ ei) {
    int t0 = blockIdx.x * 256 + threadIdx.x;
    int stride = gridDim.x * 256;
    for (int e = t0; e < EE; e += stride) {
        int src = __ldg(&ei[e]);
        int dst = __ldg(&ei[EE + e]);
        int pos = atomicAdd(&g_cursor[dst], 1);
        g_csr[pos] = src;
    }
}

// ---------------------------------------------------------------------------
// Kernel 4: BN stats via CSR. One warp per node (grid-stride).
// Lane owns channels 2*lane, 2*lane+1 (one half2 of the 128B row).
// ---------------------------------------------------------------------------
__global__ __launch_bounds__(256) void edge_stats_csr() {
    const int lane = threadIdx.x & 31;
    const int warp0 = (blockIdx.x * 256 + threadIdx.x) >> 5;
    const int nwarp = (gridDim.x * 256) >> 5;
    const unsigned* Pu = reinterpret_cast<const unsigned*>(g_Ph);
    const unsigned* Qu = reinterpret_cast<const unsigned*>(g_Qh);

    float s0 = 0.f, s1 = 0.f, q0 = 0.f, q1 = 0.f;

    for (int n = warp0; n < NN; n += nwarp) {
        int deg = g_cnt[n];
        if (deg == 0) continue;
        int start = g_off[n];
        float2 pf = __half22float2(*reinterpret_cast<const __half2*>(&Pu[n * 32 + lane]));
        for (int j = 0; j < deg; j += 32) {
            int m = min(32, deg - j);
            int my = (j + lane < deg) ? g_csr[start + j + lane] : 0;
            for (int jj = 0; jj < m; jj++) {
                int s = __shfl_sync(0xffffffffu, my, jj);
                float2 qf = __half22float2(*reinterpret_cast<const __half2*>(&Qu[s * 32 + lane]));
                float t0 = pf.x + qf.x, t1 = pf.y + qf.y;
                s0 += t0; s1 += t1;
                q0 = fmaf(t0, t0, q0);
                q1 = fmaf(t1, t1, q1);
            }
        }
    }

    __shared__ float ssum[64], ssq[64];
    if (threadIdx.x < 64) { ssum[threadIdx.x] = 0.f; ssq[threadIdx.x] = 0.f; }
    __syncthreads();
    atomicAdd(&ssum[2 * lane], s0);
    atomicAdd(&ssum[2 * lane + 1], s1);
    atomicAdd(&ssq[2 * lane], q0);
    atomicAdd(&ssq[2 * lane + 1], q1);
    __syncthreads();
    if (threadIdx.x < 64) {
        atomicAdd(&g_stats[threadIdx.x], (double)ssum[threadIdx.x]);
        atomicAdd(&g_stats[64 + threadIdx.x], (double)ssq[threadIdx.x]);
    }
}

// ---------------------------------------------------------------------------
// Kernel 5: fold BN into per-channel scale/shift (b cancels out of BN).
// ---------------------------------------------------------------------------
__global__ void bn_finalize(const float* __restrict__ gamma,
                            const float* __restrict__ beta) {
    int c = threadIdx.x;
    double inv_e = 1.0 / (double)EE;
    double mean = g_stats[c] * inv_e;
    double var = g_stats[64 + c] * inv_e - mean * mean;
    float scale = gamma[c] * rsqrtf((float)var + 1e-5f);
    g_scale[c] = scale;
    g_shift[c] = fmaf(-(float)mean, scale, beta[c]);
}

// ---------------------------------------------------------------------------
// Kernel 6: aggregation via CSR. One warp per node; register accumulation;
// single coalesced store per node. No atomics, no out memset.
// ---------------------------------------------------------------------------
__global__ __launch_bounds__(256) void agg_csr(float* __restrict__ out) {
    const int lane = threadIdx.x & 31;
    const int n = (blockIdx.x * 256 + threadIdx.x) >> 5;
    if (n >= NN) return;
    const unsigned* Pu = reinterpret_cast<const unsigned*>(g_Ph);
    const unsigned* Qu = reinterpret_cast<const unsigned*>(g_Qh);
    const float2 sc = *reinterpret_cast<const float2*>(&g_scale[2 * lane]);
    const float2 sh = *reinterpret_cast<const float2*>(&g_shift[2 * lane]);

    int deg = g_cnt[n];
    float a0 = 0.f, a1 = 0.f;
    if (deg > 0) {
        int start = g_off[n];
        float2 pf = __half22float2(*reinterpret_cast<const __half2*>(&Pu[n * 32 + lane]));
        for (int j = 0; j < deg; j += 32) {
            int m = min(32, deg - j);
            int my = (j + lane < deg) ? g_csr[start + j + lane] : 0;
            for (int jj = 0; jj < m; jj++) {
                int s = __shfl_sync(0xffffffffu, my, jj);
                float2 qf = __half22float2(*reinterpret_cast<const __half2*>(&Qu[s * 32 + lane]));
                float v0 = fmaf(pf.x + qf.x, sc.x, sh.x);
                float v1 = fmaf(pf.y + qf.y, sc.y, sh.y);
                a0 += (v0 >= 0.f ? v0 : 0.3f * v0);
                a1 += (v1 >= 0.f ? v1 : 0.3f * v1);
            }
        }
        float inv = 1.0f / (float)deg;
        a0 *= inv; a1 *= inv;
    }
    *reinterpret_cast<float2*>(&out[(size_t)n * 64 + 2 * lane]) = make_float2(a0, a1);
}

// ---------------------------------------------------------------------------
extern "C" void kernel_launch(void* const* d_in, const int* in_sizes, int n_in,
                              void* d_out, int out_size) {
    const float* feat  = (const float*)d_in[0];
    const int*   ei    = (const int*)d_in[1];
    const float* W     = (const float*)d_in[2];
    // d_in[3] = b: cancels out of BN, unused
    const float* gamma = (const float*)d_in[4];
    const float* beta  = (const float*)d_in[5];
    float* out = (float*)d_out;

    void *p_cnt, *p_stats;
    cudaGetSymbolAddress(&p_cnt, g_cnt);
    cudaGetSymbolAddress(&p_stats, g_stats);

    cudaMemsetAsync(p_cnt, 0, (size_t)NN * sizeof(int));
    cudaMemsetAsync(p_stats, 0, 128 * sizeof(double));

    gemm_pq_cnt<<<GEMM_BLOCKS + CNT_BLOCKS, 256>>>(feat, W, ei);
    scan_local<<<SCAN_BLOCKS, 1024>>>();
    scan_bsum<<<1, 128>>>();
    off_cursor<<<(NN + 255) / 256, 256>>>();
    csr_fill<<<1480, 256>>>(ei);
    edge_stats_csr<<<1184, 256>>>();
    bn_finalize<<<1, 64>>>(gamma, beta);
    agg_csr<<<(NN * 32 + 255) / 256, 256>>>(out);
}

// round 6
// speedup vs baseline: 1.5611x; 1.0401x over previous
#include <cuda_runtime.h>
#include <cuda_fp16.h>
#include <cstdint>

#define NN 100000
#define EE 1600000
#define GEMM_BLOCKS ((NN + 63) / 64)
#define CNT_BLOCKS 160
#define SCAN_BLOCKS ((NN + 1023) / 1024)   // 98

// Scratch (device globals: allocation-free)
__device__ __half g_Ph[NN * 64];   // fp16 P = feat @ (W1-W2)^T
__device__ __half g_Qh[NN * 64];   // fp16 Q = feat @ W2^T
__device__ int    g_cnt[NN];       // in-degree
__device__ int    g_off[NN];       // CSR row offsets (any disjoint layout)
__device__ int    g_cursor[NN];    // fill cursors
__device__ int    g_total;         // scan base allocator
__device__ int    g_csr[EE];       // src indices grouped by dst
__device__ double g_stats[128];    // [0:64) sum, [64:128) sumsq

// ---------------------------------------------------------------------------
// Kernel 1: heterogeneous launch: GEMM blocks + degree-count blocks.
// ---------------------------------------------------------------------------
__global__ __launch_bounds__(256) void gemm_pq_cnt(const float* __restrict__ feat,
                                                   const float* __restrict__ W,
                                                   const int* __restrict__ ei) {
    if (blockIdx.x >= GEMM_BLOCKS) {
        // degree-count blocks: int4 elements, grid-stride = total count threads
        int t0 = (blockIdx.x - GEMM_BLOCKS) * 256 + threadIdx.x;
        const int stride = CNT_BLOCKS * 256;           // one int4 per thread per step
        const int4* d4 = reinterpret_cast<const int4*>(ei + EE);
        for (int e = t0; e < EE / 4; e += stride) {
            int4 d = __ldg(&d4[e]);
            atomicAdd(&g_cnt[d.x], 1);
            atomicAdd(&g_cnt[d.y], 1);
            atomicAdd(&g_cnt[d.z], 1);
            atomicAdd(&g_cnt[d.w], 1);
        }
        return;
    }

    __shared__ float Wsh[64][128];  // [k][c']: c'<64 -> W1-W2, c'>=64 -> W2
    __shared__ float Xsh[64][64];   // [node][k]

    for (int i = threadIdx.x; i < 64 * 64; i += 256) {
        int c = i >> 6, k = i & 63;
        float w1 = W[c * 128 + k];
        float w2 = W[c * 128 + 64 + k];
        Wsh[k][c]      = w1 - w2;
        Wsh[k][64 + c] = w2;
    }
    int node0 = blockIdx.x * 64;
    for (int i = threadIdx.x; i < 64 * 16; i += 256) {
        int n = i >> 4, v = i & 15;
        int gn = node0 + n;
        if (gn >= NN) gn = NN - 1;
        float4 x = reinterpret_cast<const float4*>(feat)[gn * 16 + v];
        *reinterpret_cast<float4*>(&Xsh[n][v * 4]) = x;
    }
    __syncthreads();

    const int tx = threadIdx.x & 15;   // channel group: 8 channels
    const int ty = threadIdx.x >> 4;   // node group: 4 nodes
    float acc[4][8];
#pragma unroll
    for (int j = 0; j < 4; j++)
#pragma unroll
        for (int cc = 0; cc < 8; cc++) acc[j][cc] = 0.f;

#pragma unroll
    for (int k0 = 0; k0 < 64; k0 += 4) {
        float4 xr[4];
#pragma unroll
        for (int j = 0; j < 4; j++)
            xr[j] = *reinterpret_cast<const float4*>(&Xsh[ty * 4 + j][k0]);
#pragma unroll
        for (int kk = 0; kk < 4; kk++) {
            float4 wa = *reinterpret_cast<const float4*>(&Wsh[k0 + kk][tx * 8]);
            float4 wb = *reinterpret_cast<const float4*>(&Wsh[k0 + kk][tx * 8 + 4]);
            float w[8] = {wa.x, wa.y, wa.z, wa.w, wb.x, wb.y, wb.z, wb.w};
#pragma unroll
            for (int j = 0; j < 4; j++) {
                float xv = reinterpret_cast<const float*>(&xr[j])[kk];
#pragma unroll
                for (int cc = 0; cc < 8; cc++)
                    acc[j][cc] = fmaf(xv, w[cc], acc[j][cc]);
            }
        }
    }

    const int cbase = tx * 8;
#pragma unroll
    for (int j = 0; j < 4; j++) {
        int gn = node0 + ty * 4 + j;
        if (gn >= NN) continue;
        uint4 hv;
        *reinterpret_cast<__half2*>(&hv.x) = __floats2half2_rn(acc[j][0], acc[j][1]);
        *reinterpret_cast<__half2*>(&hv.y) = __floats2half2_rn(acc[j][2], acc[j][3]);
        *reinterpret_cast<__half2*>(&hv.z) = __floats2half2_rn(acc[j][4], acc[j][5]);
        *reinterpret_cast<__half2*>(&hv.w) = __floats2half2_rn(acc[j][6], acc[j][7]);
        __half* base = (cbase < 64) ? &g_Ph[gn * 64 + cbase]
                                    : &g_Qh[gn * 64 + (cbase - 64)];
        *reinterpret_cast<uint4*>(base) = hv;
    }
}

// ---------------------------------------------------------------------------
// Kernel 2: single-launch scan. Block bases allocated via atomic ticket
// (CSR ranges need only be disjoint, not node-ordered).
// ---------------------------------------------------------------------------
__global__ __launch_bounds__(1024) void scan_alloc() {
    __shared__ int wsum[32];
    __shared__ int gbase;
    int i = blockIdx.x * 1024 + threadIdx.x;
    int v = (i < NN) ? g_cnt[i] : 0;
    int lane = threadIdx.x & 31, wid = threadIdx.x >> 5;
    int x = v;
#pragma unroll
    for (int d = 1; d < 32; d <<= 1) {
        int y = __shfl_up_sync(0xffffffffu, x, d);
        if (lane >= d) x += y;
    }
    if (lane == 31) wsum[wid] = x;
    __syncthreads();
    if (wid == 0) {
        int w = wsum[lane];
#pragma unroll
        for (int d = 1; d < 32; d <<= 1) {
            int y = __shfl_up_sync(0xffffffffu, w, d);
            if (lane >= d) w += y;
        }
        wsum[lane] = w;
        if (lane == 31) gbase = atomicAdd(&g_total, w);
    }
    __syncthreads();
    int base = gbase + ((wid > 0) ? wsum[wid - 1] : 0);
    if (i < NN) {
        int o = base + x - v;
        g_off[i] = o;
        g_cursor[i] = o;
    }
}

// ---------------------------------------------------------------------------
// Kernel 3: CSR fill (counting-sort edges by dst), 4 edges/thread.
// ---------------------------------------------------------------------------
__global__ __launch_bounds__(256) void csr_fill(const int* __restrict__ ei) {
    int t = blockIdx.x * 256 + threadIdx.x;
    if (t >= EE / 4) return;
    const int4* s4 = reinterpret_cast<const int4*>(ei);
    const int4* d4 = reinterpret_cast<const int4*>(ei + EE);
    int4 s = __ldg(&s4[t]);
    int4 d = __ldg(&d4[t]);
    g_csr[atomicAdd(&g_cursor[d.x], 1)] = s.x;
    g_csr[atomicAdd(&g_cursor[d.y], 1)] = s.y;
    g_csr[atomicAdd(&g_cursor[d.z], 1)] = s.z;
    g_csr[atomicAdd(&g_cursor[d.w], 1)] = s.w;
}

// ---------------------------------------------------------------------------
// Kernel 4: BN stats via CSR. One warp per node; 2 edges per round.
// Lane li=lane&15 owns channels 4li..4li+3 (uint2); half h=lane>>4 -> edge.
// ---------------------------------------------------------------------------
__global__ __launch_bounds__(256) void edge_stats_csr() {
    const int lane = threadIdx.x & 31;
    const int li = lane & 15;
    const int h = lane >> 4;
    const int warp0 = (blockIdx.x * 256 + threadIdx.x) >> 5;
    const int nwarp = (gridDim.x * 256) >> 5;
    const uint2* P2 = reinterpret_cast<const uint2*>(g_Ph);
    const uint2* Q2 = reinterpret_cast<const uint2*>(g_Qh);

    float s[4] = {0.f, 0.f, 0.f, 0.f};
    float q[4] = {0.f, 0.f, 0.f, 0.f};

    for (int n = warp0; n < NN; n += nwarp) {
        int deg = g_cnt[n];
        if (deg == 0) continue;
        int start = g_off[n];
        uint2 pw = P2[n * 16 + li];
        float2 pa = __half22float2(*reinterpret_cast<const __half2*>(&pw.x));
        float2 pb = __half22float2(*reinterpret_cast<const __half2*>(&pw.y));
        for (int j = 0; j < deg; j += 32) {
            int m = min(32, deg - j);
            int my = (j + lane < deg) ? g_csr[start + j + lane] : 0;
            int m2 = (m + 1) >> 1;
            for (int i = 0; i < m2; i++) {
                int idx = 2 * i + h;
                int src = __shfl_sync(0xffffffffu, my, idx);
                if (idx < m) {
                    uint2 qw = Q2[src * 16 + li];
                    float2 qa = __half22float2(*reinterpret_cast<const __half2*>(&qw.x));
                    float2 qb = __half22float2(*reinterpret_cast<const __half2*>(&qw.y));
                    float t0 = pa.x + qa.x, t1 = pa.y + qa.y;
                    float t2 = pb.x + qb.x, t3 = pb.y + qb.y;
                    s[0] += t0; s[1] += t1; s[2] += t2; s[3] += t3;
                    q[0] = fmaf(t0, t0, q[0]);
                    q[1] = fmaf(t1, t1, q[1]);
                    q[2] = fmaf(t2, t2, q[2]);
                    q[3] = fmaf(t3, t3, q[3]);
                }
            }
        }
    }

    // fold the two halves (same channel ownership at li and li+16)
#pragma unroll
    for (int k = 0; k < 4; k++) {
        s[k] += __shfl_down_sync(0xffffffffu, s[k], 16);
        q[k] += __shfl_down_sync(0xffffffffu, q[k], 16);
    }

    __shared__ float ssum[64], ssq[64];
    if (threadIdx.x < 64) { ssum[threadIdx.x] = 0.f; ssq[threadIdx.x] = 0.f; }
    __syncthreads();
    if (h == 0) {
#pragma unroll
        for (int k = 0; k < 4; k++) {
            atomicAdd(&ssum[4 * li + k], s[k]);
            atomicAdd(&ssq[4 * li + k], q[k]);
        }
    }
    __syncthreads();
    if (threadIdx.x < 64) {
        atomicAdd(&g_stats[threadIdx.x], (double)ssum[threadIdx.x]);
        atomicAdd(&g_stats[64 + threadIdx.x], (double)ssq[threadIdx.x]);
    }
}

// ---------------------------------------------------------------------------
// Kernel 5: aggregation. Inline BN finalize in the block prologue.
// One warp per node; 2 edges per round; coalesced float4 stores.
// ---------------------------------------------------------------------------
__global__ __launch_bounds__(256) void agg_csr(float* __restrict__ out,
                                               const float* __restrict__ gamma,
                                               const float* __restrict__ beta) {
    __shared__ float sscale[64], sshift[64];
    if (threadIdx.x < 64) {
        int c = threadIdx.x;
        double inv_e = 1.0 / (double)EE;
        double mean = g_stats[c] * inv_e;
        double var = g_stats[64 + c] * inv_e - mean * mean;
        float scale = __ldg(&gamma[c]) * rsqrtf((float)var + 1e-5f);
        sscale[c] = scale;
        sshift[c] = fmaf(-(float)mean, scale, __ldg(&beta[c]));
    }
    __syncthreads();

    const int lane = threadIdx.x & 31;
    const int li = lane & 15;
    const int h = lane >> 4;
    const int n = (blockIdx.x * 256 + threadIdx.x) >> 5;
    if (n >= NN) return;
    const uint2* P2 = reinterpret_cast<const uint2*>(g_Ph);
    const uint2* Q2 = reinterpret_cast<const uint2*>(g_Qh);
    const float4 sc = *reinterpret_cast<const float4*>(&sscale[4 * li]);
    const float4 sh = *reinterpret_cast<const float4*>(&sshift[4 * li]);

    int deg = g_cnt[n];
    float a[4] = {0.f, 0.f, 0.f, 0.f};
    if (deg > 0) {
        int start = g_off[n];
        uint2 pw = P2[n * 16 + li];
        float2 pa = __half22float2(*reinterpret_cast<const __half2*>(&pw.x));
        float2 pb = __half22float2(*reinterpret_cast<const __half2*>(&pw.y));
        for (int j = 0; j < deg; j += 32) {
            int m = min(32, deg - j);
            int my = (j + lane < deg) ? g_csr[start + j + lane] : 0;
            int m2 = (m + 1) >> 1;
            for (int i = 0; i < m2; i++) {
                int idx = 2 * i + h;
                int src = __shfl_sync(0xffffffffu, my, idx);
                if (idx < m) {
                    uint2 qw = Q2[src * 16 + li];
                    float2 qa = __half22float2(*reinterpret_cast<const __half2*>(&qw.x));
                    float2 qb = __half22float2(*reinterpret_cast<const __half2*>(&qw.y));
                    float v0 = fmaf(pa.x + qa.x, sc.x, sh.x);
                    float v1 = fmaf(pa.y + qa.y, sc.y, sh.y);
                    float v2 = fmaf(pb.x + qb.x, sc.z, sh.z);
                    float v3 = fmaf(pb.y + qb.y, sc.w, sh.w);
                    a[0] += (v0 >= 0.f ? v0 : 0.3f * v0);
                    a[1] += (v1 >= 0.f ? v1 : 0.3f * v1);
                    a[2] += (v2 >= 0.f ? v2 : 0.3f * v2);
                    a[3] += (v3 >= 0.f ? v3 : 0.3f * v3);
                }
            }
        }
    }
    // fold halves
#pragma unroll
    for (int k = 0; k < 4; k++)
        a[k] += __shfl_down_sync(0xffffffffu, a[k], 16);

    if (h == 0) {
        float inv = (deg > 0) ? (1.0f / (float)deg) : 0.f;
        float4 r = make_float4(a[0] * inv, a[1] * inv, a[2] * inv, a[3] * inv);
        *reinterpret_cast<float4*>(&out[(size_t)n * 64 + 4 * li]) = r;
    }
}

// ---------------------------------------------------------------------------
extern "C" void kernel_launch(void* const* d_in, const int* in_sizes, int n_in,
                              void* d_out, int out_size) {
    const float* feat  = (const float*)d_in[0];
    const int*   ei    = (const int*)d_in[1];
    const float* W     = (const float*)d_in[2];
    // d_in[3] = b: cancels out of BN, unused
    const float* gamma = (const float*)d_in[4];
    const float* beta  = (const float*)d_in[5];
    float* out = (float*)d_out;

    void *p_cnt, *p_stats, *p_total;
    cudaGetSymbolAddress(&p_cnt, g_cnt);
    cudaGetSymbolAddress(&p_stats, g_stats);
    cudaGetSymbolAddress(&p_total, g_total);

    cudaMemsetAsync(p_cnt, 0, (size_t)NN * sizeof(int));
    cudaMemsetAsync(p_stats, 0, 128 * sizeof(double));
    cudaMemsetAsync(p_total, 0, sizeof(int));

    gemm_pq_cnt<<<GEMM_BLOCKS + CNT_BLOCKS, 256>>>(feat, W, ei);
    scan_alloc<<<SCAN_BLOCKS, 1024>>>();
    csr_fill<<<(EE / 4 + 255) / 256, 256>>>(ei);
    edge_stats_csr<<<1184, 256>>>();
    agg_csr<<<(NN * 32 + 255) / 256, 256>>>(out, gamma, beta);
}

// round 8
// speedup vs baseline: 1.6144x; 1.0342x over previous
#include <cuda_runtime.h>
#include <cuda_fp16.h>
#include <cstdint>

#define NN 100000
#define EE 1600000
#define GEMM_BLOCKS ((NN + 63) / 64)
#define CNT_BLOCKS 160
#define SCAN_BLOCKS ((NN + 1023) / 1024)   // 98

// Scratch (device globals: allocation-free)
__device__ __half g_Ph[NN * 64];   // fp16 P = feat @ (W1-W2)^T
__device__ __half g_Qh[NN * 64];   // fp16 Q = feat @ W2^T
__device__ int    g_cnt[NN];       // in-degree
__device__ int    g_off[NN];       // CSR row offsets (any disjoint layout)
__device__ int    g_cursor[NN];    // fill cursors
__device__ int    g_total;         // scan base allocator
__device__ int    g_csr[EE];       // src indices grouped by dst
__device__ double g_stats[128];    // [0:64) sum, [64:128) sumsq

#define FFMA2(acc, x, w) \
    asm("fma.rn.f32x2 %0, %1, %2, %3;" : "=l"(acc) : "l"(x), "l"(w), "l"(acc))

// ---------------------------------------------------------------------------
// Kernel 1: heterogeneous launch: GEMM blocks (f32x2 FFMA) + degree-count.
// ---------------------------------------------------------------------------
__global__ __launch_bounds__(256) void gemm_pq_cnt(const float* __restrict__ feat,
                                                   const float* __restrict__ W,
                                                   const int* __restrict__ ei) {
    if (blockIdx.x >= GEMM_BLOCKS) {
        if (blockIdx.x == GEMM_BLOCKS && threadIdx.x == 0) g_total = 0;
        int t0 = (blockIdx.x - GEMM_BLOCKS) * 256 + threadIdx.x;
        const int stride = CNT_BLOCKS * 256;
        const int4* d4 = reinterpret_cast<const int4*>(ei + EE);
        for (int e = t0; e < EE / 4; e += stride) {
            int4 d = __ldg(&d4[e]);
            atomicAdd(&g_cnt[d.x], 1);
            atomicAdd(&g_cnt[d.y], 1);
            atomicAdd(&g_cnt[d.z], 1);
            atomicAdd(&g_cnt[d.w], 1);
        }
        return;
    }

    __shared__ float Wsh[64][128];  // [k][c']: c'<64 -> W1-W2, c'>=64 -> W2
    __shared__ float Xsh[64][64];   // [node][k]

    for (int i = threadIdx.x; i < 64 * 64; i += 256) {
        int c = i >> 6, k = i & 63;
        float w1 = W[c * 128 + k];
        float w2 = W[c * 128 + 64 + k];
        Wsh[k][c]      = w1 - w2;
        Wsh[k][64 + c] = w2;
    }
    int node0 = blockIdx.x * 64;
    for (int i = threadIdx.x; i < 64 * 16; i += 256) {
        int n = i >> 4, v = i & 15;
        int gn = node0 + n;
        if (gn >= NN) gn = NN - 1;
        float4 x = reinterpret_cast<const float4*>(feat)[gn * 16 + v];
        *reinterpret_cast<float4*>(&Xsh[n][v * 4]) = x;
    }
    __syncthreads();

    const int tx = threadIdx.x & 15;   // channel group: 8 channels (4 f32x2)
    const int ty = threadIdx.x >> 4;   // node group: 4 nodes
    unsigned long long acc2[4][4] = {};

#pragma unroll
    for (int k0 = 0; k0 < 64; k0 += 4) {
        float4 xr[4];
#pragma unroll
        for (int j = 0; j < 4; j++)
            xr[j] = *reinterpret_cast<const float4*>(&Xsh[ty * 4 + j][k0]);
#pragma unroll
        for (int kk = 0; kk < 4; kk++) {
            ulonglong2 wlo = *reinterpret_cast<const ulonglong2*>(&Wsh[k0 + kk][tx * 8]);
            ulonglong2 whi = *reinterpret_cast<const ulonglong2*>(&Wsh[k0 + kk][tx * 8 + 4]);
#pragma unroll
            for (int j = 0; j < 4; j++) {
                float xv = reinterpret_cast<const float*>(&xr[j])[kk];
                unsigned long long xx;
                asm("mov.b64 %0, {%1, %1};" : "=l"(xx) : "f"(xv));
                FFMA2(acc2[j][0], xx, wlo.x);
                FFMA2(acc2[j][1], xx, wlo.y);
                FFMA2(acc2[j][2], xx, whi.x);
                FFMA2(acc2[j][3], xx, whi.y);
            }
        }
    }

    const int cbase = tx * 8;
#pragma unroll
    for (int j = 0; j < 4; j++) {
        int gn = node0 + ty * 4 + j;
        if (gn >= NN) continue;
        uint4 hv;
        unsigned* hw = reinterpret_cast<unsigned*>(&hv);
#pragma unroll
        for (int p = 0; p < 4; p++) {
            float lo, hi;
            asm("mov.b64 {%0, %1}, %2;" : "=f"(lo), "=f"(hi) : "l"(acc2[j][p]));
            *reinterpret_cast<__half2*>(&hw[p]) = __floats2half2_rn(lo, hi);
        }
        __half* base = (cbase < 64) ? &g_Ph[gn * 64 + cbase]
                                    : &g_Qh[gn * 64 + (cbase - 64)];
        *reinterpret_cast<uint4*>(base) = hv;
    }
}

// ---------------------------------------------------------------------------
// Kernel 2: single-launch scan (atomic ticket bases). Also zeroes g_stats.
// ---------------------------------------------------------------------------
__global__ __launch_bounds__(1024) void scan_alloc() {
    if (blockIdx.x == 0 && threadIdx.x < 128) g_stats[threadIdx.x] = 0.0;
    __shared__ int wsum[32];
    __shared__ int gbase;
    int i = blockIdx.x * 1024 + threadIdx.x;
    int v = (i < NN) ? g_cnt[i] : 0;
    int lane = threadIdx.x & 31, wid = threadIdx.x >> 5;
    int x = v;
#pragma unroll
    for (int d = 1; d < 32; d <<= 1) {
        int y = __shfl_up_sync(0xffffffffu, x, d);
        if (lane >= d) x += y;
    }
    if (lane == 31) wsum[wid] = x;
    __syncthreads();
    if (wid == 0) {
        int w = wsum[lane];
#pragma unroll
        for (int d = 1; d < 32; d <<= 1) {
            int y = __shfl_up_sync(0xffffffffu, w, d);
            if (lane >= d) w += y;
        }
        wsum[lane] = w;
        if (lane == 31) gbase = atomicAdd(&g_total, w);
    }
    __syncthreads();
    int base = gbase + ((wid > 0) ? wsum[wid - 1] : 0);
    if (i < NN) {
        int o = base + x - v;
        g_off[i] = o;
        g_cursor[i] = o;
    }
}

// ---------------------------------------------------------------------------
// Kernel 3: CSR fill (counting-sort edges by dst), 4 edges/thread.
// ---------------------------------------------------------------------------
__global__ __launch_bounds__(256) void csr_fill(const int* __restrict__ ei) {
    int t = blockIdx.x * 256 + threadIdx.x;
    if (t >= EE / 4) return;
    const int4* s4 = reinterpret_cast<const int4*>(ei);
    const int4* d4 = reinterpret_cast<const int4*>(ei + EE);
    int4 s = __ldg(&s4[t]);
    int4 d = __ldg(&d4[t]);
    g_csr[atomicAdd(&g_cursor[d.x], 1)] = s.x;
    g_csr[atomicAdd(&g_cursor[d.y], 1)] = s.y;
    g_csr[atomicAdd(&g_cursor[d.z], 1)] = s.z;
    g_csr[atomicAdd(&g_cursor[d.w], 1)] = s.w;
}

// ---------------------------------------------------------------------------
// Kernel 4: BN stats, decomposed:
//   sum  = sum_n deg*P[n] + sum_e Q[src]
//   sumsq= sum_n deg*P^2 + 2*sum_n P[n].R[n] + sum_e Q^2,  R[n]=sum_nbrs Q
// Inner loop touches ONLY Q: rq += q (HADD2), q2 += q*q (HFMA2).
// 8 lanes/edge (uint4 = 8 ch/lane); 4 edges per shfl round (h = lane>>3).
// ---------------------------------------------------------------------------
__global__ __launch_bounds__(256) void edge_stats_csr() {
    const int lane = threadIdx.x & 31;
    const int li = lane & 7;
    const int h = lane >> 3;
    const int warp0 = (blockIdx.x * 256 + threadIdx.x) >> 5;
    const int nwarp = (gridDim.x * 256) >> 5;

    float su[8], sq[8];
#pragma unroll
    for (int c = 0; c < 8; c++) { su[c] = 0.f; sq[c] = 0.f; }

    for (int n = warp0; n < NN; n += nwarp) {
        int deg = g_cnt[n];
        if (deg == 0) continue;
        int start = g_off[n];
        uint4 pw = *reinterpret_cast<const uint4*>(&g_Ph[n * 64 + li * 8]);
        const unsigned* pww = reinterpret_cast<const unsigned*>(&pw);

        __half2 rq2[4], qq2[4];
#pragma unroll
        for (int w = 0; w < 4; w++) {
            rq2[w] = __half2(__float2half(0.f), __float2half(0.f));
            qq2[w] = rq2[w];
        }

        for (int j = 0; j < deg; j += 32) {
            int m = min(32, deg - j);
            int my = (j + lane < deg) ? g_csr[start + j + lane] : 0;
            int m4 = (m + 3) >> 2;
            for (int i = 0; i < m4; i++) {
                int idx = 4 * i + h;
                int src = __shfl_sync(0xffffffffu, my, idx);
                if (idx < m) {
                    uint4 qw = *reinterpret_cast<const uint4*>(&g_Qh[src * 64 + li * 8]);
                    const unsigned* qww = reinterpret_cast<const unsigned*>(&qw);
#pragma unroll
                    for (int w = 0; w < 4; w++) {
                        __half2 q = *reinterpret_cast<const __half2*>(&qww[w]);
                        rq2[w] = __hadd2(rq2[w], q);
                        qq2[w] = __hfma2(q, q, qq2[w]);
                    }
                }
            }
        }

        float fdeg = (h == 0) ? (float)deg : 0.f;
#pragma unroll
        for (int w = 0; w < 4; w++) {
            float2 pf = __half22float2(*reinterpret_cast<const __half2*>(&pww[w]));
            float2 fr = __half22float2(rq2[w]);
            float2 fq = __half22float2(qq2[w]);
            // channel 2w
            su[2 * w]     = fmaf(fdeg, pf.x, su[2 * w]) + fr.x;
            float u0 = fmaf(fdeg, pf.x, fr.x + fr.x);
            sq[2 * w]     = fmaf(pf.x, u0, sq[2 * w]) + fq.x;
            // channel 2w+1
            su[2 * w + 1] = fmaf(fdeg, pf.y, su[2 * w + 1]) + fr.y;
            float u1 = fmaf(fdeg, pf.y, fr.y + fr.y);
            sq[2 * w + 1] = fmaf(pf.y, u1, sq[2 * w + 1]) + fq.y;
        }
    }

    // fold the four h-groups (same channel ownership at li, li+8, li+16, li+24)
#pragma unroll
    for (int c = 0; c < 8; c++) {
        su[c] += __shfl_down_sync(0xffffffffu, su[c], 16);
        sq[c] += __shfl_down_sync(0xffffffffu, sq[c], 16);
        su[c] += __shfl_down_sync(0xffffffffu, su[c], 8);
        sq[c] += __shfl_down_sync(0xffffffffu, sq[c], 8);
    }

    __shared__ float ssum[64], ssq[64];
    if (threadIdx.x < 64) { ssum[threadIdx.x] = 0.f; ssq[threadIdx.x] = 0.f; }
    __syncthreads();
    if (h == 0) {
#pragma unroll
        for (int c = 0; c < 8; c++) {
            atomicAdd(&ssum[li * 8 + c], su[c]);
            atomicAdd(&ssq[li * 8 + c], sq[c]);
        }
    }
    __syncthreads();
    if (threadIdx.x < 64) {
        atomicAdd(&g_stats[threadIdx.x], (double)ssum[threadIdx.x]);
        atomicAdd(&g_stats[64 + threadIdx.x], (double)ssq[threadIdx.x]);
    }
}

// ---------------------------------------------------------------------------
// Kernel 5: aggregation. Half2 datapath: t=hadd2, v=hfma2(t,sc,sh),
// leaky = hmax2(v, 0.3*v); fp32 accumulation. One warp per node,
// 8 lanes/edge, 4 edges per shfl round.
// ---------------------------------------------------------------------------
__global__ __launch_bounds__(256) void agg_csr(float* __restrict__ out,
                                               const float* __restrict__ gamma,
                                               const float* __restrict__ beta) {
    __shared__ float  fscale[64], fshift[64];
    __shared__ __half2 sscale2[32], sshift2[32];
    if (threadIdx.x < 64) {
        int c = threadIdx.x;
        double inv_e = 1.0 / (double)EE;
        double mean = g_stats[c] * inv_e;
        double var = g_stats[64 + c] * inv_e - mean * mean;
        float scale = __ldg(&gamma[c]) * rsqrtf((float)var + 1e-5f);
        fscale[c] = scale;
        fshift[c] = fmaf(-(float)mean, scale, __ldg(&beta[c]));
    }
    __syncthreads();
    if (threadIdx.x < 32) {
        int c = threadIdx.x;
        sscale2[c] = __floats2half2_rn(fscale[2 * c], fscale[2 * c + 1]);
        sshift2[c] = __floats2half2_rn(fshift[2 * c], fshift[2 * c + 1]);
    }
    __syncthreads();

    const int lane = threadIdx.x & 31;
    const int li = lane & 7;
    const int h = lane >> 3;
    const int n = (blockIdx.x * 256 + threadIdx.x) >> 5;
    if (n >= NN) return;

    __half2 sc2[4], sh2[4];
#pragma unroll
    for (int w = 0; w < 4; w++) {
        sc2[w] = sscale2[li * 4 + w];
        sh2[w] = sshift2[li * 4 + w];
    }
    const __half2 slope = __floats2half2_rn(0.3f, 0.3f);

    int deg = g_cnt[n];
    float a[8];
#pragma unroll
    for (int c = 0; c < 8; c++) a[c] = 0.f;

    if (deg > 0) {
        int start = g_off[n];
        uint4 pw = *reinterpret_cast<const uint4*>(&g_Ph[n * 64 + li * 8]);
        const unsigned* pww = reinterpret_cast<const unsigned*>(&pw);
        __half2 p2[4];
#pragma unroll
        for (int w = 0; w < 4; w++)
            p2[w] = *reinterpret_cast<const __half2*>(&pww[w]);

        for (int j = 0; j < deg; j += 32) {
            int m = min(32, deg - j);
            int my = (j + lane < deg) ? g_csr[start + j + lane] : 0;
            int m4 = (m + 3) >> 2;
            for (int i = 0; i < m4; i++) {
                int idx = 4 * i + h;
                int src = __shfl_sync(0xffffffffu, my, idx);
                if (idx < m) {
                    uint4 qw = *reinterpret_cast<const uint4*>(&g_Qh[src * 64 + li * 8]);
                    const unsigned* qww = reinterpret_cast<const unsigned*>(&qw);
#pragma unroll
                    for (int w = 0; w < 4; w++) {
                        __half2 q = *reinterpret_cast<const __half2*>(&qww[w]);
                        __half2 t = __hadd2(p2[w], q);
                        __half2 v = __hfma2(t, sc2[w], sh2[w]);
                        __half2 y = __hmax2(v, __hmul2(v, slope));
                        float2 yf = __half22float2(y);
                        a[2 * w]     += yf.x;
                        a[2 * w + 1] += yf.y;
                    }
                }
            }
        }
    }

    // fold the four h-groups
#pragma unroll
    for (int c = 0; c < 8; c++) {
        a[c] += __shfl_down_sync(0xffffffffu, a[c], 16);
        a[c] += __shfl_down_sync(0xffffffffu, a[c], 8);
    }

    if (h == 0) {
        float inv = (deg > 0) ? (1.0f / (float)deg) : 0.f;
        float4 r0 = make_float4(a[0] * inv, a[1] * inv, a[2] * inv, a[3] * inv);
        float4 r1 = make_float4(a[4] * inv, a[5] * inv, a[6] * inv, a[7] * inv);
        float4* dst = reinterpret_cast<float4*>(&out[(size_t)n * 64 + li * 8]);
        dst[0] = r0;
        dst[1] = r1;
    }
}

// ---------------------------------------------------------------------------
extern "C" void kernel_launch(void* const* d_in, const int* in_sizes, int n_in,
                              void* d_out, int out_size) {
    const float* feat  = (const float*)d_in[0];
    const int*   ei    = (const int*)d_in[1];
    const float* W     = (const float*)d_in[2];
    // d_in[3] = b: cancels out of BN, unused
    const float* gamma = (const float*)d_in[4];
    const float* beta  = (const float*)d_in[5];
    float* out = (float*)d_out;

    void* p_cnt;
    cudaGetSymbolAddress(&p_cnt, g_cnt);
    cudaMemsetAsync(p_cnt, 0, (size_t)NN * sizeof(int));

    gemm_pq_cnt<<<GEMM_BLOCKS + CNT_BLOCKS, 256>>>(feat, W, ei);
    scan_alloc<<<SCAN_BLOCKS, 1024>>>();
    csr_fill<<<(EE / 4 + 255) / 256, 256>>>(ei);
    edge_stats_csr<<<1184, 256>>>();
    agg_csr<<<(NN * 32 + 255) / 256, 256>>>(out, gamma, beta);
}